// round 11
// baseline (speedup 1.0000x reference)
#include <cuda_runtime.h>
#include <mma.h>
#include <cstdint>
#include <cstddef>

using namespace nvcuda;

#define S_LEN 512
#define BSZ   64
#define IDIM  512
#define HDIM  512
#define NG    2048          // 4*H
#define NBLK_REC 128        // 64 per direction
#define REC_THREADS 256

// ---- scratch (device globals: allocation-guard safe) ----
__device__ float g_xg[2][S_LEN][BSZ][NG];   // 512 MB: X@W^T + Wb + Rb, per dir/time
__device__ float g_h[2][2][BSZ][HDIM];      // ping-pong h buffers [buf][dir][b][j]
__device__ unsigned int g_cnt[2][513];      // per-dir step counters; [512]=init. Monotonic, never reset.

static const size_t Y_ELEMS  = (size_t)S_LEN * 2 * BSZ * HDIM; // 33,554,432
static const size_t YH_OFF_C = Y_ELEMS;
static const size_t YC_OFF_C = Y_ELEMS + (size_t)2 * BSZ * HDIM;

#define PART_LD 40          // partials leading dim: 160B = multiple of 16B (wmma-legal)
#define RS_LD   264         // resident R_s leading dim (1056B, 16B-multiple, 8 mod 32 banks)

// smem float offsets
#define H_S_OFF   0
#define H_S_SZ    (64 * 520)            // 33280
#define R_S_OFF   (H_S_SZ)              // 33280
#define R_S_SZ    (32 * RS_LD)          // 8448
#define PART_OFF  (H_S_SZ + R_S_SZ)     // 41728
#define PART_SZ   (8 * 32 * PART_LD)    // 10240
#define SMEM_FLOATS (PART_OFF + PART_SZ) // 51968 -> 207,872 bytes

__device__ __forceinline__ float sigmoidf_(float x) { return 1.0f / (1.0f + __expf(-x)); }

__device__ __forceinline__ unsigned int ld_acq_u32(const unsigned int* p) {
    unsigned int v;
    asm volatile("ld.acquire.gpu.global.u32 %0, [%1];" : "=r"(v) : "l"(p) : "memory");
    return v;
}
__device__ __forceinline__ void red_rel_add(unsigned int* p, unsigned int v) {
    asm volatile("red.release.gpu.global.add.u32 [%0], %1;" :: "l"(p), "r"(v) : "memory");
}

// ============================================================================
// Kernel A: Xg[d][s][b][n] = sum_k X[s][b][k] * W[d][n][k] + Wb[d][n] + Rb[d][n]
// ============================================================================
__global__ void __launch_bounds__(256)
xg_gemm(const float* __restrict__ X, const float* __restrict__ W,
        const float* __restrict__ Bias)
{
    const int d  = blockIdx.z;
    const int n0 = blockIdx.x * 64;
    const int m0 = blockIdx.y * 64;

    __shared__ float As[64][40];
    __shared__ float Bs[64][40];
    __shared__ float Cs[64][72];

    const int tid = threadIdx.x;
    const int w   = tid >> 5;
    const int wm  = w >> 1;
    const int wn  = w & 1;

    wmma::fragment<wmma::accumulator, 16, 16, 8, float> acc0, acc1;
    wmma::fill_fragment(acc0, 0.0f);
    wmma::fill_fragment(acc1, 0.0f);

    const float* Wd = W + (size_t)d * NG * IDIM;

    for (int k0 = 0; k0 < IDIM; k0 += 32) {
        for (int i = tid; i < 512; i += 256) {
            int r  = i >> 3;
            int kk = (i & 7) << 2;
            float4 va = *(const float4*)(X  + (size_t)(m0 + r) * IDIM + k0 + kk);
            *(float4*)&As[r][kk] = va;
            float4 vb = *(const float4*)(Wd + (size_t)(n0 + r) * IDIM + k0 + kk);
            *(float4*)&Bs[r][kk] = vb;
        }
        __syncthreads();

        #pragma unroll
        for (int kk = 0; kk < 32; kk += 8) {
            wmma::fragment<wmma::matrix_a, 16, 16, 8, wmma::precision::tf32, wmma::row_major> af;
            wmma::load_matrix_sync(af, &As[wm * 16][kk], 40);
            #pragma unroll
            for (int e = 0; e < af.num_elements; e++) af.x[e] = wmma::__float_to_tf32(af.x[e]);

            wmma::fragment<wmma::matrix_b, 16, 16, 8, wmma::precision::tf32, wmma::col_major> bf0, bf1;
            wmma::load_matrix_sync(bf0, &Bs[wn * 32][kk], 40);
            wmma::load_matrix_sync(bf1, &Bs[wn * 32 + 16][kk], 40);
            #pragma unroll
            for (int e = 0; e < bf0.num_elements; e++) {
                bf0.x[e] = wmma::__float_to_tf32(bf0.x[e]);
                bf1.x[e] = wmma::__float_to_tf32(bf1.x[e]);
            }
            wmma::mma_sync(acc0, af, bf0, acc0);
            wmma::mma_sync(acc1, af, bf1, acc1);
        }
        __syncthreads();
    }

    wmma::store_matrix_sync(&Cs[wm * 16][wn * 32],      acc0, 72, wmma::mem_row_major);
    wmma::store_matrix_sync(&Cs[wm * 16][wn * 32 + 16], acc1, 72, wmma::mem_row_major);
    __syncthreads();

    const float* bd = Bias + (size_t)d * 4096;
    float* xgd = &g_xg[d][0][0][0];
    for (int i = tid; i < 4096; i += 256) {
        int r = i >> 6, c = i & 63;
        int n = n0 + c;
        xgd[(size_t)(m0 + r) * NG + n] = Cs[r][c] + bd[n] + bd[2048 + n];
    }
}

// ============================================================================
// Kernel B: persistent bidirectional recurrence.
//  - 128 blocks: dir = blk/64, 8 hidden cols each (32 gate rows of R).
//  - 8 warps = 2(m-half) x 4(k-split of 128).
//  - R: HALF in registers (ks 0..7 of each slice, 64 regs), HALF resident in
//    smem R_s (k offsets 64..127 of each slice, packed 32 x 256, ldm 264),
//    loaded as fragments per step.  <- de-spills regs (was 253 regs, spilling)
//  - Pair-chunked h staging (ld.cg + named pair barrier), k-split partials in
//    smem (ldm 40), grid sync via elected red.release / ld.acquire poll.
// ============================================================================
__global__ void __launch_bounds__(REC_THREADS, 1)
lstm_rec(const float* __restrict__ R, const int* __restrict__ seqlen,
         const float* __restrict__ h0g, const float* __restrict__ c0g,
         const float* __restrict__ P, float* __restrict__ out)
{
    extern __shared__ __align__(128) float sm[];
    float* h_s  = sm + H_S_OFF;       // 64 x 520 (loop); R staging (init)
    float* R_s  = sm + R_S_OFF;       // 32 x 264 packed (resident half of R)
    float* part = sm + PART_OFF;      // 8 x 32 x PART_LD

    const int tid = threadIdx.x;
    const int d   = (int)(blockIdx.x >> 6);
    const int j0  = (int)(blockIdx.x & 63) << 3;

    const int wid = tid >> 5;
    const int wm  = wid & 1;          // m-half: rows wm*32..+32
    const int wk  = wid >> 1;         // k-slice: k in [wk*128, wk*128+128)

    // ---- baseline counter read (MUST precede our init arrive) ----
    const unsigned int base = ld_acq_u32(&g_cnt[d][0]);
    const unsigned int target = base + 64;

    // ---- stage full R slice into h_s temporarily (32 x 520) ----
    const float* Rd = R + (size_t)d * NG * HDIM;
    for (int i = tid; i < 4096; i += REC_THREADS) {       // 32*512/4 float4
        int c = i >> 7, k = (i & 127) << 2;
        int rrow = (c >> 3) * HDIM + j0 + (c & 7);
        *(float4*)&h_s[c * 520 + k] = *(const float4*)(Rd + (size_t)rrow * HDIM + k);
    }
    // init ping buffer 0 with initial_h for this chunk (st.cg: consumers use ld.cg)
    for (int i = tid; i < 512; i += REC_THREADS) {
        int b = i >> 3, jj = i & 7;
        __stcg(&g_h[0][d][b][j0 + jj], h0g[(size_t)(d * BSZ + b) * HDIM + j0 + jj]);
    }
    __syncthreads();

    // ---- resident register B fragments: ks 0..7 of this warp's k slice ----
    wmma::fragment<wmma::matrix_b, 16, 16, 8, wmma::precision::tf32, wmma::col_major> bfr[8][2];
    #pragma unroll
    for (int ks = 0; ks < 8; ks++) {
        #pragma unroll
        for (int nh = 0; nh < 2; nh++) {
            wmma::load_matrix_sync(bfr[ks][nh], &h_s[(nh * 16) * 520 + wk * 128 + ks * 8], 520);
            #pragma unroll
            for (int e = 0; e < bfr[ks][nh].num_elements; e++)
                bfr[ks][nh].x[e] = wmma::__float_to_tf32(bfr[ks][nh].x[e]);
        }
    }
    // ---- copy upper k-halves (k offsets 64..127 of each slice) into R_s packed ----
    // R_s[r][ws*64 + kk] = Rfull[r][ws*128 + 64 + kk],  ws=0..3, kk=0..63
    for (int i = tid; i < 2048; i += REC_THREADS) {       // 32*256/4 float4
        int r = i >> 6, kq = (i & 63) << 2;               // kq in [0,256) step 4
        int ws = kq >> 6, kk = kq & 63;
        *(float4*)&R_s[r * RS_LD + kq] = *(const float4*)&h_s[r * 520 + ws * 128 + 64 + kk];
    }

    // ---- per-thread cell state ----
    const int jj = tid & 7;
    const int b0 = tid >> 3;       // 0..31
    const int b1 = b0 + 32;
    const int jg = j0 + jj;
    const float Pi = P[(size_t)d * 1536 + jg];
    const float Pf = P[(size_t)d * 1536 + 512 + jg];
    const float Po = P[(size_t)d * 1536 + 1024 + jg];
    const int sl0 = seqlen[b0], sl1 = seqlen[b1];
    const float h00 = h0g[(size_t)(d * BSZ + b0) * HDIM + jg];
    const float h01 = h0g[(size_t)(d * BSZ + b1) * HDIM + jg];
    const float c00 = c0g[(size_t)(d * BSZ + b0) * HDIM + jg];
    const float c01 = c0g[(size_t)(d * BSZ + b1) * HDIM + jg];
    float cr0 = c00, cr1 = c01;

    __syncthreads();                                  // bfr loads + R_s copy done before h_s reuse
    if (tid == 0) red_rel_add(&g_cnt[d][512], 1u);    // init arrive (release)

    const int pair_tid = tid & 63;                    // thread id within 2-warp pair

    for (int step = 0; step < S_LEN; step++) {
        const int cur = step & 1, nxt = cur ^ 1;
        const int t = (d == 0) ? step : (S_LEN - 1 - step);
        const float* xg = &g_xg[d][t][0][0];

        // prefetch xg gate values (DRAM, streaming) — independent of barrier
        float xv0[4], xv1[4];
        #pragma unroll
        for (int g = 0; g < 4; g++) {
            xv0[g] = __ldcs(xg + (size_t)b0 * NG + g * 512 + jg);
            xv1[g] = __ldcs(xg + (size_t)b1 * NG + g * 512 + jg);
        }

        // wait: all 64 blocks of this direction finished producing g_h[cur]
        if (tid == 0) {
            const unsigned int* cp = &g_cnt[d][(step == 0) ? 512 : (step - 1)];
            while (ld_acq_u32(cp) != target) { }
        }
        __syncthreads();

        // stage this pair's 32KB h chunk: rows 0..63, k in [wk*128,+128)
        const float* hsrc = &g_h[cur][d][0][0];
        {
            const int kbase = wk * 128;
            #pragma unroll
            for (int i = pair_tid; i < 2048; i += 64) {     // 2048 float4 per chunk
                int b = i >> 5, kq = (i & 31) << 2;
                float4 v = __ldcg((const float4*)(hsrc + (size_t)b * HDIM + kbase + kq));
                *(float4*)&h_s[b * 520 + kbase + kq] = v;
            }
        }
        asm volatile("bar.sync %0, %1;" :: "r"(wk + 1), "r"(64) : "memory");

        // mma: warp computes partial C[wm*32:+32, 0:32] over k slice [wk*128,+128)
        wmma::fragment<wmma::accumulator, 16, 16, 8, float> acc[2][2];
        #pragma unroll
        for (int mh = 0; mh < 2; mh++)
            #pragma unroll
            for (int nh = 0; nh < 2; nh++)
                wmma::fill_fragment(acc[mh][nh], 0.0f);

        #pragma unroll
        for (int ks = 0; ks < 16; ks++) {
            wmma::fragment<wmma::matrix_a, 16, 16, 8, wmma::precision::tf32, wmma::row_major> af0, af1;
            wmma::load_matrix_sync(af0, &h_s[(wm * 32) * 520      + wk * 128 + ks * 8], 520);
            wmma::load_matrix_sync(af1, &h_s[(wm * 32 + 16) * 520 + wk * 128 + ks * 8], 520);
            #pragma unroll
            for (int e = 0; e < af0.num_elements; e++) {
                af0.x[e] = wmma::__float_to_tf32(af0.x[e]);
                af1.x[e] = wmma::__float_to_tf32(af1.x[e]);
            }
            if (ks < 8) {
                wmma::mma_sync(acc[0][0], af0, bfr[ks][0], acc[0][0]);
                wmma::mma_sync(acc[0][1], af0, bfr[ks][1], acc[0][1]);
                wmma::mma_sync(acc[1][0], af1, bfr[ks][0], acc[1][0]);
                wmma::mma_sync(acc[1][1], af1, bfr[ks][1], acc[1][1]);
            } else {
                // load B fragments for this ks from resident R_s (packed upper halves)
                wmma::fragment<wmma::matrix_b, 16, 16, 8, wmma::precision::tf32, wmma::col_major> bf0, bf1;
                const int kp = wk * 64 + (ks - 8) * 8;
                wmma::load_matrix_sync(bf0, &R_s[kp], RS_LD);
                wmma::load_matrix_sync(bf1, &R_s[16 * RS_LD + kp], RS_LD);
                #pragma unroll
                for (int e = 0; e < bf0.num_elements; e++) {
                    bf0.x[e] = wmma::__float_to_tf32(bf0.x[e]);
                    bf1.x[e] = wmma::__float_to_tf32(bf1.x[e]);
                }
                wmma::mma_sync(acc[0][0], af0, bf0, acc[0][0]);
                wmma::mma_sync(acc[0][1], af0, bf1, acc[0][1]);
                wmma::mma_sync(acc[1][0], af1, bf0, acc[1][0]);
                wmma::mma_sync(acc[1][1], af1, bf1, acc[1][1]);
            }
        }

        // store k-split partials: part[wid] is [32][PART_LD]
        {
            float* pw = part + wid * (32 * PART_LD);
            #pragma unroll
            for (int mh = 0; mh < 2; mh++)
                #pragma unroll
                for (int nh = 0; nh < 2; nh++)
                    wmma::store_matrix_sync(pw + (mh * 16) * PART_LD + nh * 16, acc[mh][nh],
                                            PART_LD, wmma::mem_row_major);
        }
        __syncthreads();

        // reduce 4 k-partials + fused cell update
        {
            const int wmsel0 = b0 >> 5, row0 = b0 & 31;   // 0
            const int wmsel1 = b1 >> 5, row1 = b1 & 31;   // 1
            float gs0[4], gs1[4];
            #pragma unroll
            for (int g = 0; g < 4; g++) {
                const int c = g * 8 + jj;
                float s0 = 0.f, s1 = 0.f;
                #pragma unroll
                for (int kw = 0; kw < 4; kw++) {
                    s0 += part[((kw << 1) | wmsel0) * (32 * PART_LD) + row0 * PART_LD + c];
                    s1 += part[((kw << 1) | wmsel1) * (32 * PART_LD) + row1 * PART_LD + c];
                }
                gs0[g] = s0; gs1[g] = s1;
            }

            // pair 0
            {
                float gi = gs0[0] + xv0[0];
                float go = gs0[1] + xv0[1];
                float gf = gs0[2] + xv0[2];
                float gc = gs0[3] + xv0[3];
                float it = sigmoidf_(gi + Pi * cr0);
                float ft = sigmoidf_(gf + Pf * cr0);
                float cn = ft * cr0 + it * tanhf(gc);
                float ot = sigmoidf_(go + Po * cn);
                float hn = ot * tanhf(cn);
                if (t >= sl0) { hn = h00; cn = c00; }
                cr0 = cn;
                __stcg(&g_h[nxt][d][b0][jg], hn);
                __stcs(out + ((size_t)(t * 2 + d) * BSZ + b0) * HDIM + jg, hn);
                if (step == S_LEN - 1) {
                    out[YH_OFF_C + (size_t)(d * BSZ + b0) * HDIM + jg] = hn;
                    out[YC_OFF_C + (size_t)(d * BSZ + b0) * HDIM + jg] = cn;
                }
            }
            // pair 1
            {
                float gi = gs1[0] + xv1[0];
                float go = gs1[1] + xv1[1];
                float gf = gs1[2] + xv1[2];
                float gc = gs1[3] + xv1[3];
                float it = sigmoidf_(gi + Pi * cr1);
                float ft = sigmoidf_(gf + Pf * cr1);
                float cn = ft * cr1 + it * tanhf(gc);
                float ot = sigmoidf_(go + Po * cn);
                float hn = ot * tanhf(cn);
                if (t >= sl1) { hn = h01; cn = c01; }
                cr1 = cn;
                __stcg(&g_h[nxt][d][b1][jg], hn);
                __stcs(out + ((size_t)(t * 2 + d) * BSZ + b1) * HDIM + jg, hn);
                if (step == S_LEN - 1) {
                    out[YH_OFF_C + (size_t)(d * BSZ + b1) * HDIM + jg] = hn;
                    out[YC_OFF_C + (size_t)(d * BSZ + b1) * HDIM + jg] = cn;
                }
            }
        }

        __syncthreads();                                    // all h writes + partial reads done
        if (tid == 0) red_rel_add(&g_cnt[d][step], 1u);     // arrive (release)
    }
}

// ============================================================================
extern "C" void kernel_launch(void* const* d_in, const int* in_sizes, int n_in,
                              void* d_out, int out_size)
{
    const float* X    = (const float*)d_in[0];  // (512, 64, 512)
    const float* W    = (const float*)d_in[1];  // (2, 2048, 512)
    const float* R    = (const float*)d_in[2];  // (2, 2048, 512)
    const float* Bias = (const float*)d_in[3];  // (2, 4096)
    const int*   seq  = (const int*)  d_in[4];  // (64,)
    const float* h0   = (const float*)d_in[5];  // (2, 64, 512)
    const float* c0   = (const float*)d_in[6];  // (2, 64, 512)
    const float* P    = (const float*)d_in[7];  // (2, 1536)
    float* out = (float*)d_out;

    // Phase 1: input projection (+ both biases folded in)
    dim3 gA(NG / 64, (S_LEN * BSZ) / 64, 2);
    xg_gemm<<<gA, 256>>>(X, W, Bias);

    // Phase 2: persistent recurrence
    const int smem_bytes = SMEM_FLOATS * (int)sizeof(float);   // 207,872
    cudaFuncSetAttribute(lstm_rec, cudaFuncAttributeMaxDynamicSharedMemorySize, smem_bytes);
    lstm_rec<<<NBLK_REC, REC_THREADS, smem_bytes>>>(R, seq, h0, c0, P, out);
}

// round 12
// speedup vs baseline: 1.4864x; 1.4864x over previous
#include <cuda_runtime.h>
#include <cuda_fp16.h>
#include <mma.h>
#include <cstdint>
#include <cstddef>

using namespace nvcuda;

#define S_LEN 512
#define BSZ   64
#define IDIM  512
#define HDIM  512
#define NG    2048          // 4*H
#define NBLK_REC 128        // 64 per direction
#define REC_THREADS 256

// ---- scratch (device globals: allocation-guard safe) ----
__device__ float g_xg[2][S_LEN][BSZ][NG];                     // 512 MB fp32 gate pre-acts
__device__ __align__(128) __half g_h16[2][2][BSZ][HDIM];      // ping-pong h (fp16)
__device__ unsigned int g_cnt[2][513];                        // per-dir monotonic step counters

static const size_t Y_ELEMS  = (size_t)S_LEN * 2 * BSZ * HDIM; // 33,554,432
static const size_t YH_OFF_C = Y_ELEMS;
static const size_t YC_OFF_C = Y_ELEMS + (size_t)2 * BSZ * HDIM;

#define PART_LD 40              // fp32 partials ld: 160B (16B-multiple, wmma-legal)
#define HS_LD   536             // h_s / R staging ld in halves: 1072B -> LDSM conflict-free
#define H_S_BYTES  (64 * HS_LD * 2)            // 68,608 (128B-multiple)
#define PART_BYTES (8 * 32 * PART_LD * 4)      // 40,960
#define SMEM_BYTES (H_S_BYTES + PART_BYTES)    // 109,568

__device__ __forceinline__ float sigmoidf_(float x) { return 1.0f / (1.0f + __expf(-x)); }

__device__ __forceinline__ unsigned int ld_acq_u32(const unsigned int* p) {
    unsigned int v;
    asm volatile("ld.acquire.gpu.global.u32 %0, [%1];" : "=r"(v) : "l"(p) : "memory");
    return v;
}
__device__ __forceinline__ void red_rel_add(unsigned int* p, unsigned int v) {
    asm volatile("red.release.gpu.global.add.u32 [%0], %1;" :: "l"(p), "r"(v) : "memory");
}
__device__ __forceinline__ void st_cg_u16(__half* p, __half v) {
    unsigned short u = __half_as_ushort(v);
    asm volatile("st.global.cg.u16 [%0], %1;" :: "l"(p), "h"(u) : "memory");
}

// ============================================================================
// Kernel A: Xg[d][s][b][n] = sum_k X[s][b][k] * W[d][n][k] + Wb[d][n] + Rb[d][n]
// (unchanged — tf32 wmma, proven)
// ============================================================================
__global__ void __launch_bounds__(256)
xg_gemm(const float* __restrict__ X, const float* __restrict__ W,
        const float* __restrict__ Bias)
{
    const int d  = blockIdx.z;
    const int n0 = blockIdx.x * 64;
    const int m0 = blockIdx.y * 64;

    __shared__ float As[64][40];
    __shared__ float Bs[64][40];
    __shared__ float Cs[64][72];

    const int tid = threadIdx.x;
    const int w   = tid >> 5;
    const int wm  = w >> 1;
    const int wn  = w & 1;

    wmma::fragment<wmma::accumulator, 16, 16, 8, float> acc0, acc1;
    wmma::fill_fragment(acc0, 0.0f);
    wmma::fill_fragment(acc1, 0.0f);

    const float* Wd = W + (size_t)d * NG * IDIM;

    for (int k0 = 0; k0 < IDIM; k0 += 32) {
        for (int i = tid; i < 512; i += 256) {
            int r  = i >> 3;
            int kk = (i & 7) << 2;
            float4 va = *(const float4*)(X  + (size_t)(m0 + r) * IDIM + k0 + kk);
            *(float4*)&As[r][kk] = va;
            float4 vb = *(const float4*)(Wd + (size_t)(n0 + r) * IDIM + k0 + kk);
            *(float4*)&Bs[r][kk] = vb;
        }
        __syncthreads();

        #pragma unroll
        for (int kk = 0; kk < 32; kk += 8) {
            wmma::fragment<wmma::matrix_a, 16, 16, 8, wmma::precision::tf32, wmma::row_major> af;
            wmma::load_matrix_sync(af, &As[wm * 16][kk], 40);
            #pragma unroll
            for (int e = 0; e < af.num_elements; e++) af.x[e] = wmma::__float_to_tf32(af.x[e]);

            wmma::fragment<wmma::matrix_b, 16, 16, 8, wmma::precision::tf32, wmma::col_major> bf0, bf1;
            wmma::load_matrix_sync(bf0, &Bs[wn * 32][kk], 40);
            wmma::load_matrix_sync(bf1, &Bs[wn * 32 + 16][kk], 40);
            #pragma unroll
            for (int e = 0; e < bf0.num_elements; e++) {
                bf0.x[e] = wmma::__float_to_tf32(bf0.x[e]);
                bf1.x[e] = wmma::__float_to_tf32(bf1.x[e]);
            }
            wmma::mma_sync(acc0, af, bf0, acc0);
            wmma::mma_sync(acc1, af, bf1, acc1);
        }
        __syncthreads();
    }

    wmma::store_matrix_sync(&Cs[wm * 16][wn * 32],      acc0, 72, wmma::mem_row_major);
    wmma::store_matrix_sync(&Cs[wm * 16][wn * 32 + 16], acc1, 72, wmma::mem_row_major);
    __syncthreads();

    const float* bd = Bias + (size_t)d * 4096;
    float* xgd = &g_xg[d][0][0][0];
    for (int i = tid; i < 4096; i += 256) {
        int r = i >> 6, c = i & 63;
        int n = n0 + c;
        xgd[(size_t)(m0 + r) * NG + n] = Cs[r][c] + bd[n] + bd[2048 + n];
    }
}

// ============================================================================
// Kernel B: persistent bidirectional recurrence — fp16 operands, fp32 accum.
//  - 128 blocks: dir = blk/64, 8 hidden cols each (32 gate rows of R).
//  - 8 warps = 2(m-half) x 4(k-split of 128). fp16 m16n16k16: 8 ks per slice.
//  - FULL R slice as register B fragments: bfr[8][2] = 64 regs (fits now).
//  - h stored fp16 in global (.cg both sides), staged to smem per k-chunk.
//  - fp32 partials (ldm 40) + fused cell in fp32; grid sync as round 9.
// ============================================================================
__global__ void __launch_bounds__(REC_THREADS, 1)
lstm_rec(const float* __restrict__ R, const int* __restrict__ seqlen,
         const float* __restrict__ h0g, const float* __restrict__ c0g,
         const float* __restrict__ P, float* __restrict__ out)
{
    extern __shared__ __align__(128) char smem_raw[];
    __half* h_s  = (__half*)smem_raw;                       // 64 x HS_LD halves (loop); R staging (init)
    float*  part = (float*)(smem_raw + H_S_BYTES);          // 8 x 32 x PART_LD fp32

    const int tid = threadIdx.x;
    const int d   = (int)(blockIdx.x >> 6);
    const int j0  = (int)(blockIdx.x & 63) << 3;

    const int wid = tid >> 5;
    const int wm  = wid & 1;          // m-half: rows wm*32..+32
    const int wk  = wid >> 1;         // k-slice: k in [wk*128, wk*128+128)

    // ---- baseline counter read (MUST precede our init arrive) ----
    const unsigned int base = ld_acq_u32(&g_cnt[d][0]);
    const unsigned int target = base + 64;

    // ---- stage R slice into h_s as fp16 (32 rows x 512 k) ----
    const float* Rd = R + (size_t)d * NG * HDIM;
    for (int i = tid; i < 4096; i += REC_THREADS) {       // 32*512/4 float4
        int c = i >> 7, k = (i & 127) << 2;
        int rrow = (c >> 3) * HDIM + j0 + (c & 7);
        float4 v = *(const float4*)(Rd + (size_t)rrow * HDIM + k);
        __half2* dst = (__half2*)&h_s[c * HS_LD + k];
        dst[0] = __floats2half2_rn(v.x, v.y);
        dst[1] = __floats2half2_rn(v.z, v.w);
    }
    // init ping buffer 0 with initial_h (fp16, .cg)
    for (int i = tid; i < 512; i += REC_THREADS) {
        int b = i >> 3, jj = i & 7;
        float hv = h0g[(size_t)(d * BSZ + b) * HDIM + j0 + jj];
        st_cg_u16(&g_h16[0][d][b][j0 + jj], __float2half_rn(hv));
    }
    __syncthreads();

    // ---- FULL R slice as register B fragments: 8 ks x 2 n-halves ----
    wmma::fragment<wmma::matrix_b, 16, 16, 16, __half, wmma::col_major> bfr[8][2];
    #pragma unroll
    for (int ks = 0; ks < 8; ks++) {
        #pragma unroll
        for (int nh = 0; nh < 2; nh++)
            wmma::load_matrix_sync(bfr[ks][nh], &h_s[(nh * 16) * HS_LD + wk * 128 + ks * 16], HS_LD);
    }

    // ---- per-thread cell state ----
    const int jj = tid & 7;
    const int b0 = tid >> 3;       // 0..31
    const int b1 = b0 + 32;
    const int jg = j0 + jj;
    const float Pi = P[(size_t)d * 1536 + jg];
    const float Pf = P[(size_t)d * 1536 + 512 + jg];
    const float Po = P[(size_t)d * 1536 + 1024 + jg];
    const int sl0 = seqlen[b0], sl1 = seqlen[b1];
    const float h00 = h0g[(size_t)(d * BSZ + b0) * HDIM + jg];
    const float h01 = h0g[(size_t)(d * BSZ + b1) * HDIM + jg];
    const float c00 = c0g[(size_t)(d * BSZ + b0) * HDIM + jg];
    const float c01 = c0g[(size_t)(d * BSZ + b1) * HDIM + jg];
    float cr0 = c00, cr1 = c01;

    __syncthreads();                                  // bfr loads done before h_s reuse
    if (tid == 0) red_rel_add(&g_cnt[d][512], 1u);    // init arrive (release)

    const int pair_tid = tid & 63;                    // thread id within 2-warp pair

    for (int step = 0; step < S_LEN; step++) {
        const int cur = step & 1, nxt = cur ^ 1;
        const int t = (d == 0) ? step : (S_LEN - 1 - step);
        const float* xg = &g_xg[d][t][0][0];

        // prefetch xg gate values (DRAM, streaming) — independent of barrier
        float xv0[4], xv1[4];
        #pragma unroll
        for (int g = 0; g < 4; g++) {
            xv0[g] = __ldcs(xg + (size_t)b0 * NG + g * 512 + jg);
            xv1[g] = __ldcs(xg + (size_t)b1 * NG + g * 512 + jg);
        }

        // wait: all 64 blocks of this direction finished producing g_h16[cur]
        if (tid == 0) {
            const unsigned int* cp = &g_cnt[d][(step == 0) ? 512 : (step - 1)];
            while (ld_acq_u32(cp) != target) { }
        }
        __syncthreads();

        // stage this pair's h chunk (fp16): rows 0..63, k in [wk*128,+128)
        const __half* hsrc = &g_h16[cur][d][0][0];
        {
            const int kbase = wk * 128;
            #pragma unroll
            for (int i = pair_tid; i < 1024; i += 64) {     // 1024 uint4 (8 halves each)
                int b = i >> 4, kq = (i & 15) << 3;          // kq: halves, step 8
                uint4 v = __ldcg((const uint4*)(hsrc + (size_t)b * HDIM + kbase + kq));
                *(uint4*)&h_s[b * HS_LD + kbase + kq] = v;
            }
        }
        asm volatile("bar.sync %0, %1;" :: "r"(wk + 1), "r"(64) : "memory");

        // mma: warp computes partial C[wm*32:+32, 0:32] over its 128-k slice
        wmma::fragment<wmma::accumulator, 16, 16, 16, float> acc[2][2];
        #pragma unroll
        for (int mh = 0; mh < 2; mh++)
            #pragma unroll
            for (int nh = 0; nh < 2; nh++)
                wmma::fill_fragment(acc[mh][nh], 0.0f);

        #pragma unroll
        for (int ks = 0; ks < 8; ks++) {
            wmma::fragment<wmma::matrix_a, 16, 16, 16, __half, wmma::row_major> af0, af1;
            wmma::load_matrix_sync(af0, &h_s[(wm * 32) * HS_LD      + wk * 128 + ks * 16], HS_LD);
            wmma::load_matrix_sync(af1, &h_s[(wm * 32 + 16) * HS_LD + wk * 128 + ks * 16], HS_LD);
            wmma::mma_sync(acc[0][0], af0, bfr[ks][0], acc[0][0]);
            wmma::mma_sync(acc[0][1], af0, bfr[ks][1], acc[0][1]);
            wmma::mma_sync(acc[1][0], af1, bfr[ks][0], acc[1][0]);
            wmma::mma_sync(acc[1][1], af1, bfr[ks][1], acc[1][1]);
        }

        // store k-split partials: part[wid] is [32][PART_LD]
        {
            float* pw = part + wid * (32 * PART_LD);
            #pragma unroll
            for (int mh = 0; mh < 2; mh++)
                #pragma unroll
                for (int nh = 0; nh < 2; nh++)
                    wmma::store_matrix_sync(pw + (mh * 16) * PART_LD + nh * 16, acc[mh][nh],
                                            PART_LD, wmma::mem_row_major);
        }
        __syncthreads();

        // reduce 4 k-partials + fused cell update (fp32)
        {
            const int wmsel0 = b0 >> 5, row0 = b0 & 31;
            const int wmsel1 = b1 >> 5, row1 = b1 & 31;
            float gs0[4], gs1[4];
            #pragma unroll
            for (int g = 0; g < 4; g++) {
                const int c = g * 8 + jj;
                float s0 = 0.f, s1 = 0.f;
                #pragma unroll
                for (int kw = 0; kw < 4; kw++) {
                    s0 += part[((kw << 1) | wmsel0) * (32 * PART_LD) + row0 * PART_LD + c];
                    s1 += part[((kw << 1) | wmsel1) * (32 * PART_LD) + row1 * PART_LD + c];
                }
                gs0[g] = s0; gs1[g] = s1;
            }

            // pair 0
            {
                float gi = gs0[0] + xv0[0];
                float go = gs0[1] + xv0[1];
                float gf = gs0[2] + xv0[2];
                float gc = gs0[3] + xv0[3];
                float it = sigmoidf_(gi + Pi * cr0);
                float ft = sigmoidf_(gf + Pf * cr0);
                float cn = ft * cr0 + it * tanhf(gc);
                float ot = sigmoidf_(go + Po * cn);
                float hn = ot * tanhf(cn);
                if (t >= sl0) { hn = h00; cn = c00; }
                cr0 = cn;
                st_cg_u16(&g_h16[nxt][d][b0][jg], __float2half_rn(hn));
                __stcs(out + ((size_t)(t * 2 + d) * BSZ + b0) * HDIM + jg, hn);
                if (step == S_LEN - 1) {
                    out[YH_OFF_C + (size_t)(d * BSZ + b0) * HDIM + jg] = hn;
                    out[YC_OFF_C + (size_t)(d * BSZ + b0) * HDIM + jg] = cn;
                }
            }
            // pair 1
            {
                float gi = gs1[0] + xv1[0];
                float go = gs1[1] + xv1[1];
                float gf = gs1[2] + xv1[2];
                float gc = gs1[3] + xv1[3];
                float it = sigmoidf_(gi + Pi * cr1);
                float ft = sigmoidf_(gf + Pf * cr1);
                float cn = ft * cr1 + it * tanhf(gc);
                float ot = sigmoidf_(go + Po * cn);
                float hn = ot * tanhf(cn);
                if (t >= sl1) { hn = h01; cn = c01; }
                cr1 = cn;
                st_cg_u16(&g_h16[nxt][d][b1][jg], __float2half_rn(hn));
                __stcs(out + ((size_t)(t * 2 + d) * BSZ + b1) * HDIM + jg, hn);
                if (step == S_LEN - 1) {
                    out[YH_OFF_C + (size_t)(d * BSZ + b1) * HDIM + jg] = hn;
                    out[YC_OFF_C + (size_t)(d * BSZ + b1) * HDIM + jg] = cn;
                }
            }
        }

        __syncthreads();                                    // all h writes + partial reads done
        if (tid == 0) red_rel_add(&g_cnt[d][step], 1u);     // arrive (release)
    }
}

// ============================================================================
extern "C" void kernel_launch(void* const* d_in, const int* in_sizes, int n_in,
                              void* d_out, int out_size)
{
    const float* X    = (const float*)d_in[0];  // (512, 64, 512)
    const float* W    = (const float*)d_in[1];  // (2, 2048, 512)
    const float* R    = (const float*)d_in[2];  // (2, 2048, 512)
    const float* Bias = (const float*)d_in[3];  // (2, 4096)
    const int*   seq  = (const int*)  d_in[4];  // (64,)
    const float* h0   = (const float*)d_in[5];  // (2, 64, 512)
    const float* c0   = (const float*)d_in[6];  // (2, 64, 512)
    const float* P    = (const float*)d_in[7];  // (2, 1536)
    float* out = (float*)d_out;

    // Phase 1: input projection (+ both biases folded in)
    dim3 gA(NG / 64, (S_LEN * BSZ) / 64, 2);
    xg_gemm<<<gA, 256>>>(X, W, Bias);

    // Phase 2: persistent recurrence (fp16 operands)
    cudaFuncSetAttribute(lstm_rec, cudaFuncAttributeMaxDynamicSharedMemorySize, SMEM_BYTES);
    lstm_rec<<<NBLK_REC, REC_THREADS, SMEM_BYTES>>>(R, seq, h0, c0, P, out);
}

// round 17
// speedup vs baseline: 2.5458x; 1.7127x over previous
#include <cuda_runtime.h>
#include <cuda_fp16.h>
#include <mma.h>
#include <cstdint>
#include <cstddef>

using namespace nvcuda;

#define S_LEN 512
#define BSZ   64
#define IDIM  512
#define HDIM  512
#define NG    2048          // 4*H
#define NBLK_REC 128        // 64 per direction
#define REC_THREADS 256

// ---- scratch (device globals: allocation-guard safe) ----
__device__ float g_xg[2][S_LEN][BSZ][NG];                     // 512 MB fp32 gate pre-acts
__device__ __align__(128) __half g_h16[2][2][BSZ][HDIM];      // ping-pong h (fp16)
__device__ unsigned int g_cnt[2][513];                        // per-dir monotonic step counters
__device__ __align__(128) __half g_x16[(size_t)S_LEN * BSZ * IDIM];  // 32 MB X in fp16
__device__ __align__(128) __half g_w16[(size_t)2 * NG * IDIM];       // 4 MB  W in fp16

static const size_t Y_ELEMS  = (size_t)S_LEN * 2 * BSZ * HDIM; // 33,554,432
static const size_t YH_OFF_C = Y_ELEMS;
static const size_t YC_OFF_C = Y_ELEMS + (size_t)2 * BSZ * HDIM;

#define PART_LD 40              // fp32 partials ld: 160B (16B-multiple, wmma-legal)
#define HS_LD   536             // h_s ld in halves: 1072B
#define H_S_BYTES  (64 * HS_LD * 2)            // 68,608
#define PART_BYTES (8 * 32 * PART_LD * 4)      // 40,960
#define SMEM_BYTES (H_S_BYTES + PART_BYTES)    // 109,568

// xg fp16 GEMM tile config
#define GLD 72                                  // smem ld (halves): 144B, 16B-multiple
#define G_AB_BYTES (128 * GLD * 2)              // 18,432 per operand
#define G_SMEM_BYTES (8 * 32 * GLD * 4)         // 73,728 (C overlay; > 2*A/B = 36,864)

__device__ __forceinline__ float sigmoidf_(float x) { return 1.0f / (1.0f + __expf(-x)); }

__device__ __forceinline__ unsigned int ld_acq_u32(const unsigned int* p) {
    unsigned int v;
    asm volatile("ld.acquire.gpu.global.u32 %0, [%1];" : "=r"(v) : "l"(p) : "memory");
    return v;
}
__device__ __forceinline__ void red_rel_add(unsigned int* p, unsigned int v) {
    asm volatile("red.release.gpu.global.add.u32 [%0], %1;" :: "l"(p), "r"(v) : "memory");
}
__device__ __forceinline__ void st_cg_u16(__half* p, __half v) {
    unsigned short u = __half_as_ushort(v);
    asm volatile("st.global.cg.u16 [%0], %1;" :: "l"(p), "h"(u) : "memory");
}

// ============================================================================
// fp32 -> fp16 conversion (elementwise, float4-vectorized)
// ============================================================================
__global__ void __launch_bounds__(256)
cvt_fp16(const float* __restrict__ src, __half* __restrict__ dst, int n4)
{
    int i = blockIdx.x * 256 + threadIdx.x;
    if (i < n4) {
        float4 v = ((const float4*)src)[i];
        __half2* d2 = (__half2*)(dst + (size_t)i * 4);
        d2[0] = __floats2half2_rn(v.x, v.y);
        d2[1] = __floats2half2_rn(v.z, v.w);
    }
}

// ============================================================================
// Kernel A (fp16): Xg[d][m][n] = sum_k X16[m][k] * W16[d][n][k] + Wb[n] + Rb[n]
// 128x128 tile, BK=64, 8 warps as 4(m) x 2(n), warp tile 32x64 (2x4 frags).
// Epilogue: per-warp smem C slice (overlaying A/B), bias fused, coalesced STG.
// ============================================================================
__global__ void __launch_bounds__(256)
xg_gemm16(const __half* __restrict__ X16, const __half* __restrict__ W16,
          const float* __restrict__ Bias)
{
    extern __shared__ __align__(128) char gsm[];
    __half* As = (__half*)gsm;                         // 128 x GLD
    __half* Bs = (__half*)(gsm + G_AB_BYTES);          // 128 x GLD
    float*  Cw = (float*)gsm;                          // per-warp 32 x GLD fp32 slices

    const int d  = blockIdx.z;
    const int n0 = blockIdx.x * 128;
    const int m0 = blockIdx.y * 128;
    const int tid  = threadIdx.x;
    const int w    = tid >> 5;
    const int lane = tid & 31;
    const int wm   = w >> 1;       // 0..3 (m)
    const int wn   = w & 1;        // 0..1 (n)

    wmma::fragment<wmma::accumulator, 16, 16, 16, float> acc[2][4];
    #pragma unroll
    for (int mh = 0; mh < 2; mh++)
        #pragma unroll
        for (int nh = 0; nh < 4; nh++)
            wmma::fill_fragment(acc[mh][nh], 0.0f);

    const __half* Xb  = X16 + (size_t)m0 * IDIM;
    const __half* Wb6 = W16 + (size_t)d * NG * IDIM + (size_t)n0 * IDIM;

    for (int k0 = 0; k0 < IDIM; k0 += 64) {
        // load A/B tiles: 128 rows x 64 halves each = 1024 uint4 each
        for (int i = tid; i < 1024; i += 256) {
            int r = i >> 3, kq = (i & 7) << 3;
            *(uint4*)&As[r * GLD + kq] = *(const uint4*)(Xb  + (size_t)r * IDIM + k0 + kq);
            *(uint4*)&Bs[r * GLD + kq] = *(const uint4*)(Wb6 + (size_t)r * IDIM + k0 + kq);
        }
        __syncthreads();

        #pragma unroll
        for (int kk = 0; kk < 64; kk += 16) {
            wmma::fragment<wmma::matrix_a, 16, 16, 16, __half, wmma::row_major> af0, af1;
            wmma::load_matrix_sync(af0, &As[(wm * 32)      * GLD + kk], GLD);
            wmma::load_matrix_sync(af1, &As[(wm * 32 + 16) * GLD + kk], GLD);
            #pragma unroll
            for (int nh = 0; nh < 4; nh++) {
                wmma::fragment<wmma::matrix_b, 16, 16, 16, __half, wmma::col_major> bf;
                wmma::load_matrix_sync(bf, &Bs[(wn * 64 + nh * 16) * GLD + kk], GLD);
                wmma::mma_sync(acc[0][nh], af0, bf, acc[0][nh]);
                wmma::mma_sync(acc[1][nh], af1, bf, acc[1][nh]);
            }
        }
        __syncthreads();     // all warps done reading before next overwrite (or epilogue)
    }

    // epilogue: warp-private C slice in smem (safe to overlay A/B after final sync)
    float* cw = Cw + w * (32 * GLD);
    #pragma unroll
    for (int mh = 0; mh < 2; mh++)
        #pragma unroll
        for (int nh = 0; nh < 4; nh++)
            wmma::store_matrix_sync(cw + (mh * 16) * GLD + nh * 16, acc[mh][nh], GLD,
                                    wmma::mem_row_major);
    __syncwarp();

    const float* bd = Bias + (size_t)d * 4096;
    const int nA = n0 + wn * 64 + lane;
    const int nB = nA + 32;
    const float biasA = bd[nA] + bd[2048 + nA];
    const float biasB = bd[nB] + bd[2048 + nB];
    float* xgd = &g_xg[d][0][0][0];
    #pragma unroll 4
    for (int r = 0; r < 32; r++) {
        const size_t m = (size_t)(m0 + wm * 32 + r);
        xgd[m * NG + nA] = cw[r * GLD + lane]      + biasA;
        xgd[m * NG + nB] = cw[r * GLD + lane + 32] + biasB;
    }
}

// ============================================================================
// Kernel B: persistent bidirectional recurrence — fp16 operands, fp32 accum.
// (byte-identical to round 12 — verified win)
// ============================================================================
__global__ void __launch_bounds__(REC_THREADS, 1)
lstm_rec(const float* __restrict__ R, const int* __restrict__ seqlen,
         const float* __restrict__ h0g, const float* __restrict__ c0g,
         const float* __restrict__ P, float* __restrict__ out)
{
    extern __shared__ __align__(128) char smem_raw[];
    __half* h_s  = (__half*)smem_raw;                       // 64 x HS_LD halves (loop); R staging (init)
    float*  part = (float*)(smem_raw + H_S_BYTES);          // 8 x 32 x PART_LD fp32

    const int tid = threadIdx.x;
    const int d   = (int)(blockIdx.x >> 6);
    const int j0  = (int)(blockIdx.x & 63) << 3;

    const int wid = tid >> 5;
    const int wm  = wid & 1;          // m-half: rows wm*32..+32
    const int wk  = wid >> 1;         // k-slice: k in [wk*128, wk*128+128)

    // ---- baseline counter read (MUST precede our init arrive) ----
    const unsigned int base = ld_acq_u32(&g_cnt[d][0]);
    const unsigned int target = base + 64;

    // ---- stage R slice into h_s as fp16 (32 rows x 512 k) ----
    const float* Rd = R + (size_t)d * NG * HDIM;
    for (int i = tid; i < 4096; i += REC_THREADS) {       // 32*512/4 float4
        int c = i >> 7, k = (i & 127) << 2;
        int rrow = (c >> 3) * HDIM + j0 + (c & 7);
        float4 v = *(const float4*)(Rd + (size_t)rrow * HDIM + k);
        __half2* dst = (__half2*)&h_s[c * HS_LD + k];
        dst[0] = __floats2half2_rn(v.x, v.y);
        dst[1] = __floats2half2_rn(v.z, v.w);
    }
    // init ping buffer 0 with initial_h (fp16, .cg)
    for (int i = tid; i < 512; i += REC_THREADS) {
        int b = i >> 3, jj = i & 7;
        float hv = h0g[(size_t)(d * BSZ + b) * HDIM + j0 + jj];
        st_cg_u16(&g_h16[0][d][b][j0 + jj], __float2half_rn(hv));
    }
    __syncthreads();

    // ---- FULL R slice as register B fragments: 8 ks x 2 n-halves ----
    wmma::fragment<wmma::matrix_b, 16, 16, 16, __half, wmma::col_major> bfr[8][2];
    #pragma unroll
    for (int ks = 0; ks < 8; ks++) {
        #pragma unroll
        for (int nh = 0; nh < 2; nh++)
            wmma::load_matrix_sync(bfr[ks][nh], &h_s[(nh * 16) * HS_LD + wk * 128 + ks * 16], HS_LD);
    }

    // ---- per-thread cell state ----
    const int jj = tid & 7;
    const int b0 = tid >> 3;       // 0..31
    const int b1 = b0 + 32;
    const int jg = j0 + jj;
    const float Pi = P[(size_t)d * 1536 + jg];
    const float Pf = P[(size_t)d * 1536 + 512 + jg];
    const float Po = P[(size_t)d * 1536 + 1024 + jg];
    const int sl0 = seqlen[b0], sl1 = seqlen[b1];
    const float h00 = h0g[(size_t)(d * BSZ + b0) * HDIM + jg];
    const float h01 = h0g[(size_t)(d * BSZ + b1) * HDIM + jg];
    const float c00 = c0g[(size_t)(d * BSZ + b0) * HDIM + jg];
    const float c01 = c0g[(size_t)(d * BSZ + b1) * HDIM + jg];
    float cr0 = c00, cr1 = c01;

    __syncthreads();                                  // bfr loads done before h_s reuse
    if (tid == 0) red_rel_add(&g_cnt[d][512], 1u);    // init arrive (release)

    const int pair_tid = tid & 63;                    // thread id within 2-warp pair

    for (int step = 0; step < S_LEN; step++) {
        const int cur = step & 1, nxt = cur ^ 1;
        const int t = (d == 0) ? step : (S_LEN - 1 - step);
        const float* xg = &g_xg[d][t][0][0];

        // prefetch xg gate values (DRAM, streaming) — independent of barrier
        float xv0[4], xv1[4];
        #pragma unroll
        for (int g = 0; g < 4; g++) {
            xv0[g] = __ldcs(xg + (size_t)b0 * NG + g * 512 + jg);
            xv1[g] = __ldcs(xg + (size_t)b1 * NG + g * 512 + jg);
        }

        // wait: all 64 blocks of this direction finished producing g_h16[cur]
        if (tid == 0) {
            const unsigned int* cp = &g_cnt[d][(step == 0) ? 512 : (step - 1)];
            while (ld_acq_u32(cp) != target) { }
        }
        __syncthreads();

        // stage this pair's h chunk (fp16): rows 0..63, k in [wk*128,+128)
        const __half* hsrc = &g_h16[cur][d][0][0];
        {
            const int kbase = wk * 128;
            #pragma unroll
            for (int i = pair_tid; i < 1024; i += 64) {     // 1024 uint4 (8 halves each)
                int b = i >> 4, kq = (i & 15) << 3;          // kq: halves, step 8
                uint4 v = __ldcg((const uint4*)(hsrc + (size_t)b * HDIM + kbase + kq));
                *(uint4*)&h_s[b * HS_LD + kbase + kq] = v;
            }
        }
        asm volatile("bar.sync %0, %1;" :: "r"(wk + 1), "r"(64) : "memory");

        // mma: warp computes partial C[wm*32:+32, 0:32] over its 128-k slice
        wmma::fragment<wmma::accumulator, 16, 16, 16, float> acc[2][2];
        #pragma unroll
        for (int mh = 0; mh < 2; mh++)
            #pragma unroll
            for (int nh = 0; nh < 2; nh++)
                wmma::fill_fragment(acc[mh][nh], 0.0f);

        #pragma unroll
        for (int ks = 0; ks < 8; ks++) {
            wmma::fragment<wmma::matrix_a, 16, 16, 16, __half, wmma::row_major> af0, af1;
            wmma::load_matrix_sync(af0, &h_s[(wm * 32) * HS_LD      + wk * 128 + ks * 16], HS_LD);
            wmma::load_matrix_sync(af1, &h_s[(wm * 32 + 16) * HS_LD + wk * 128 + ks * 16], HS_LD);
            wmma::mma_sync(acc[0][0], af0, bfr[ks][0], acc[0][0]);
            wmma::mma_sync(acc[0][1], af0, bfr[ks][1], acc[0][1]);
            wmma::mma_sync(acc[1][0], af1, bfr[ks][0], acc[1][0]);
            wmma::mma_sync(acc[1][1], af1, bfr[ks][1], acc[1][1]);
        }

        // store k-split partials: part[wid] is [32][PART_LD]
        {
            float* pw = part + wid * (32 * PART_LD);
            #pragma unroll
            for (int mh = 0; mh < 2; mh++)
                #pragma unroll
                for (int nh = 0; nh < 2; nh++)
                    wmma::store_matrix_sync(pw + (mh * 16) * PART_LD + nh * 16, acc[mh][nh],
                                            PART_LD, wmma::mem_row_major);
        }
        __syncthreads();

        // reduce 4 k-partials + fused cell update (fp32)
        {
            const int wmsel0 = b0 >> 5, row0 = b0 & 31;
            const int wmsel1 = b1 >> 5, row1 = b1 & 31;
            float gs0[4], gs1[4];
            #pragma unroll
            for (int g = 0; g < 4; g++) {
                const int c = g * 8 + jj;
                float s0 = 0.f, s1 = 0.f;
                #pragma unroll
                for (int kw = 0; kw < 4; kw++) {
                    s0 += part[((kw << 1) | wmsel0) * (32 * PART_LD) + row0 * PART_LD + c];
                    s1 += part[((kw << 1) | wmsel1) * (32 * PART_LD) + row1 * PART_LD + c];
                }
                gs0[g] = s0; gs1[g] = s1;
            }

            // pair 0
            {
                float gi = gs0[0] + xv0[0];
                float go = gs0[1] + xv0[1];
                float gf = gs0[2] + xv0[2];
                float gc = gs0[3] + xv0[3];
                float it = sigmoidf_(gi + Pi * cr0);
                float ft = sigmoidf_(gf + Pf * cr0);
                float cn = ft * cr0 + it * tanhf(gc);
                float ot = sigmoidf_(go + Po * cn);
                float hn = ot * tanhf(cn);
                if (t >= sl0) { hn = h00; cn = c00; }
                cr0 = cn;
                st_cg_u16(&g_h16[nxt][d][b0][jg], __float2half_rn(hn));
                __stcs(out + ((size_t)(t * 2 + d) * BSZ + b0) * HDIM + jg, hn);
                if (step == S_LEN - 1) {
                    out[YH_OFF_C + (size_t)(d * BSZ + b0) * HDIM + jg] = hn;
                    out[YC_OFF_C + (size_t)(d * BSZ + b0) * HDIM + jg] = cn;
                }
            }
            // pair 1
            {
                float gi = gs1[0] + xv1[0];
                float go = gs1[1] + xv1[1];
                float gf = gs1[2] + xv1[2];
                float gc = gs1[3] + xv1[3];
                float it = sigmoidf_(gi + Pi * cr1);
                float ft = sigmoidf_(gf + Pf * cr1);
                float cn = ft * cr1 + it * tanhf(gc);
                float ot = sigmoidf_(go + Po * cn);
                float hn = ot * tanhf(cn);
                if (t >= sl1) { hn = h01; cn = c01; }
                cr1 = cn;
                st_cg_u16(&g_h16[nxt][d][b1][jg], __float2half_rn(hn));
                __stcs(out + ((size_t)(t * 2 + d) * BSZ + b1) * HDIM + jg, hn);
                if (step == S_LEN - 1) {
                    out[YH_OFF_C + (size_t)(d * BSZ + b1) * HDIM + jg] = hn;
                    out[YC_OFF_C + (size_t)(d * BSZ + b1) * HDIM + jg] = cn;
                }
            }
        }

        __syncthreads();                                    // all h writes + partial reads done
        if (tid == 0) red_rel_add(&g_cnt[d][step], 1u);     // arrive (release)
    }
}

// ============================================================================
extern "C" void kernel_launch(void* const* d_in, const int* in_sizes, int n_in,
                              void* d_out, int out_size)
{
    const float* X    = (const float*)d_in[0];  // (512, 64, 512)
    const float* W    = (const float*)d_in[1];  // (2, 2048, 512)
    const float* R    = (const float*)d_in[2];  // (2, 2048, 512)
    const float* Bias = (const float*)d_in[3];  // (2, 4096)
    const int*   seq  = (const int*)  d_in[4];  // (64,)
    const float* h0   = (const float*)d_in[5];  // (2, 64, 512)
    const float* c0   = (const float*)d_in[6];  // (2, 64, 512)
    const float* P    = (const float*)d_in[7];  // (2, 1536)
    float* out = (float*)d_out;

    // Phase 0: fp32 -> fp16 conversion of X and W
    {
        const int nx4 = (S_LEN * BSZ * IDIM) / 4;       // 4,194,304
        const int nw4 = (2 * NG * IDIM) / 4;            // 524,288
        __half* x16p; __half* w16p;
        cudaGetSymbolAddress((void**)&x16p, g_x16);
        cudaGetSymbolAddress((void**)&w16p, g_w16);
        cvt_fp16<<<(nx4 + 255) / 256, 256>>>(X, x16p, nx4);
        cvt_fp16<<<(nw4 + 255) / 256, 256>>>(W, w16p, nw4);

        // Phase 1: input projection in fp16 (+ both biases folded in)
        dim3 gA(NG / 128, (S_LEN * BSZ) / 128, 2);      // (16, 256, 2)
        cudaFuncSetAttribute(xg_gemm16, cudaFuncAttributeMaxDynamicSharedMemorySize, G_SMEM_BYTES);
        xg_gemm16<<<gA, 256, G_SMEM_BYTES>>>(x16p, w16p, Bias);
    }

    // Phase 2: persistent recurrence (fp16 operands)
    cudaFuncSetAttribute(lstm_rec, cudaFuncAttributeMaxDynamicSharedMemorySize, SMEM_BYTES);
    lstm_rec<<<NBLK_REC, REC_THREADS, SMEM_BYTES>>>(R, seq, h0, c0, P, out);
}